// round 13
// baseline (speedup 1.0000x reference)
#include <cuda_runtime.h>
#include <math.h>
#include <stdint.h>

#define HH 8
#define HD 32
#define BB 4
#define NN 2048
#define DD 256
#define BH (BB*HH)   // 32

// ---- device scratch (static: allocation-free rule) ----
__device__ float g_Q[(size_t)BH*NN*HD];
__device__ float g_K[(size_t)BH*NN*HD];
__device__ uint32_t g_P[(size_t)BH*NN*NN/2];   // bf16 pairs, 256 MB
__device__ float g_rowsum[BH*NN];
__device__ float g_t0[(size_t)BH*NN*HD];
__device__ float g_t1[(size_t)BH*NN*HD];
__device__ float g_acc[(size_t)BH*NN*HD];

__device__ __forceinline__ uint32_t f2tf(float f) {
    uint32_t r;
    asm("cvt.rna.tf32.f32 %0, %1;" : "=r"(r) : "f"(f));
    return r;
}

// pack two fp32 -> bf16x2 (lo in low half, hi in high half)
__device__ __forceinline__ uint32_t pack_bf16(float lo, float hi) {
    uint32_t r;
    asm("cvt.rn.bf16x2.f32 %0, %1, %2;" : "=r"(r) : "f"(hi), "f"(lo));
    return r;
}

__device__ __forceinline__ void mma_tf32(float& d0, float& d1, float& d2, float& d3,
                                         uint32_t a0, uint32_t a1, uint32_t a2, uint32_t a3,
                                         uint32_t b0, uint32_t b1) {
    asm("mma.sync.aligned.m16n8k8.row.col.f32.tf32.tf32.f32 "
        "{%0,%1,%2,%3},{%4,%5,%6,%7},{%8,%9},{%0,%1,%2,%3};"
        : "+f"(d0), "+f"(d1), "+f"(d2), "+f"(d3)
        : "r"(a0), "r"(a1), "r"(a2), "r"(a3), "r"(b0), "r"(b1));
}

__device__ __forceinline__ void mma_bf16(float& d0, float& d1, float& d2, float& d3,
                                         uint32_t a0, uint32_t a1, uint32_t a2, uint32_t a3,
                                         uint32_t b0, uint32_t b1) {
    asm("mma.sync.aligned.m16n8k16.row.col.f32.bf16.bf16.f32 "
        "{%0,%1,%2,%3},{%4,%5,%6,%7},{%8,%9},{%0,%1,%2,%3};"
        : "+f"(d0), "+f"(d1), "+f"(d2), "+f"(d3)
        : "r"(a0), "r"(a1), "r"(a2), "r"(a3), "r"(b0), "r"(b1));
}

__device__ __forceinline__ void cp16(uint32_t saddr, const void* gptr) {
    asm volatile("cp.async.cg.shared.global [%0], [%1], 16;" :: "r"(saddr), "l"(gptr));
}

// ============================================================
// Kernel 1: QKV projection + head split, 3xTF32 tensor path.
// grid (64, 4, 3): 128-row x 64-col tiles, z = which matrix.
// ============================================================
__global__ void qkv_kernel(const float* __restrict__ x,
                           const float* __restrict__ Wq, const float* __restrict__ bq,
                           const float* __restrict__ Wk, const float* __restrict__ bk,
                           const float* __restrict__ Wv, const float* __restrict__ bv,
                           const float* __restrict__ coeffs) {
    const int mat = blockIdx.z;
    const float* W    = (mat == 0) ? Wq : ((mat == 1) ? Wk : Wv);
    const float* bias = (mat == 0) ? bq : ((mat == 1) ? bk : bv);
    const int m0 = blockIdx.x * 128;
    const int c0 = blockIdx.y * 64;

    __shared__ uint32_t XsH[128][36];
    __shared__ uint32_t XsL[128][36];
    __shared__ uint32_t WtH[64][36];
    __shared__ uint32_t WtL[64][36];

    const int tid  = threadIdx.x;
    const int warp = tid >> 5;
    const int lane = tid & 31;
    const int g  = lane >> 2;
    const int qd = lane & 3;
    const int row_l = warp * 16 + g;

    float acc[8][4];
    #pragma unroll
    for (int j = 0; j < 8; j++) {
        acc[j][0]=0.f; acc[j][1]=0.f; acc[j][2]=0.f; acc[j][3]=0.f;
    }

    for (int k0 = 0; k0 < DD; k0 += 32) {
        for (int l = tid; l < 1024; l += 256) {
            int r = l >> 3, kq = l & 7;
            float4 v = *(const float4*)(x + (size_t)(m0 + r) * DD + k0 + kq * 4);
            uint32_t hx = f2tf(v.x), hy = f2tf(v.y), hz = f2tf(v.z), hw = f2tf(v.w);
            XsH[r][kq*4+0] = hx; XsH[r][kq*4+1] = hy;
            XsH[r][kq*4+2] = hz; XsH[r][kq*4+3] = hw;
            XsL[r][kq*4+0] = f2tf(v.x - __uint_as_float(hx));
            XsL[r][kq*4+1] = f2tf(v.y - __uint_as_float(hy));
            XsL[r][kq*4+2] = f2tf(v.z - __uint_as_float(hz));
            XsL[r][kq*4+3] = f2tf(v.w - __uint_as_float(hw));
        }
        for (int l = tid; l < 2048; l += 256) {
            int c = l & 63, k = l >> 6;
            float w = W[(size_t)(k0 + k) * DD + c0 + c];
            uint32_t h = f2tf(w);
            WtH[c][k] = h;
            WtL[c][k] = f2tf(w - __uint_as_float(h));
        }
        __syncthreads();

        #pragma unroll
        for (int kc = 0; kc < 32; kc += 8) {
            uint32_t aH0 = XsH[row_l    ][kc + qd];
            uint32_t aH1 = XsH[row_l + 8][kc + qd];
            uint32_t aH2 = XsH[row_l    ][kc + qd + 4];
            uint32_t aH3 = XsH[row_l + 8][kc + qd + 4];
            uint32_t aL0 = XsL[row_l    ][kc + qd];
            uint32_t aL1 = XsL[row_l + 8][kc + qd];
            uint32_t aL2 = XsL[row_l    ][kc + qd + 4];
            uint32_t aL3 = XsL[row_l + 8][kc + qd + 4];
            #pragma unroll
            for (int j = 0; j < 8; j++) {
                uint32_t bH0 = WtH[j*8 + g][kc + qd];
                uint32_t bH1 = WtH[j*8 + g][kc + qd + 4];
                uint32_t bL0 = WtL[j*8 + g][kc + qd];
                uint32_t bL1 = WtL[j*8 + g][kc + qd + 4];
                mma_tf32(acc[j][0], acc[j][1], acc[j][2], acc[j][3],
                         aH0, aH1, aH2, aH3, bH0, bH1);
                mma_tf32(acc[j][0], acc[j][1], acc[j][2], acc[j][3],
                         aH0, aH1, aH2, aH3, bL0, bL1);
                mma_tf32(acc[j][0], acc[j][1], acc[j][2], acc[j][3],
                         aL0, aL1, aL2, aL3, bH0, bH1);
            }
        }
        __syncthreads();
    }

    #pragma unroll
    for (int j = 0; j < 8; j++) {
        #pragma unroll
        for (int half = 0; half < 2; half++) {
            int m = m0 + row_l + half * 8;
            int b_ = m >> 11, n = m & 2047;
            #pragma unroll
            for (int p = 0; p < 2; p++) {
                int c = c0 + j*8 + qd*2 + p;
                float val = acc[j][half*2 + p] + bias[c];
                int h = c >> 5, d = c & 31;
                size_t idx = ((size_t)(b_ * HH + h) * NN + n) * HD + d;
                if (mat == 0)      g_Q[idx] = val;
                else if (mat == 1) g_K[idx] = val;
                else {
                    g_t0[idx]  = val;
                    g_acc[idx] = coeffs[h * 4] * val;   // c0 * v
                }
            }
        }
    }
}

// ============================================================
// Kernel 2: P = exp(Q K^T * scale) -> bf16 + rowsums.
// cp.async double-buffered K staging; K fed as raw fp32 (tf32-truncated).
// grid (16 row-tiles of 128, 32 bh), block 256 (8 warps).
// ============================================================
__global__ void attnP_kernel() {
    const int bh = blockIdx.y;
    const int r0 = blockIdx.x * 128;

    __shared__ uint32_t Qs[128][36];      // tf32 (rna), scale folded
    __shared__ uint32_t Ks[2][128][36];   // raw fp32 bits via cp.async

    const int tid  = threadIdx.x;
    const int warp = tid >> 5;
    const int lane = tid & 31;
    const int g  = lane >> 2;   // 0..7
    const int qd = lane & 3;    // 0..3

    const float scale = 0.17677669529663687f;  // 1/sqrt(32), folded into Q

    const float* Qb = g_Q + ((size_t)bh * NN + r0) * HD;
    const float* Kb = g_K + (size_t)bh * NN * HD;

    for (int l = tid; l < 1024; l += 256) {
        int r = l >> 3, kq = l & 7;
        uint32_t s = (uint32_t)__cvta_generic_to_shared(&Ks[0][r][kq*4]);
        cp16(s, Kb + (size_t)r * HD + kq * 4);
    }
    asm volatile("cp.async.commit_group;");

    for (int l = tid; l < 1024; l += 256) {
        int r = l >> 3, kq = l & 7;
        float4 v = *(const float4*)(Qb + (size_t)r * HD + kq * 4);
        uint4 u;
        u.x = f2tf(v.x * scale); u.y = f2tf(v.y * scale);
        u.z = f2tf(v.z * scale); u.w = f2tf(v.w * scale);
        *(uint4*)&Qs[r][kq*4] = u;
    }

    const int row_l = warp * 16 + g;
    float rs_lo = 0.f, rs_hi = 0.f;

    for (int ct = 0; ct < 16; ct++) {
        const int c0 = ct * 128;
        const int buf = ct & 1;

        if (ct < 15) {
            const float* Kn = Kb + (size_t)(c0 + 128) * HD;
            for (int l = tid; l < 1024; l += 256) {
                int r = l >> 3, kq = l & 7;
                uint32_t s = (uint32_t)__cvta_generic_to_shared(&Ks[buf^1][r][kq*4]);
                cp16(s, Kn + (size_t)r * HD + kq * 4);
            }
            asm volatile("cp.async.commit_group;");
        }

        if (ct < 15) { asm volatile("cp.async.wait_group 1;"); }
        else         { asm volatile("cp.async.wait_group 0;"); }
        __syncthreads();

        float acc[16][4];
        #pragma unroll
        for (int j = 0; j < 16; j++) {
            acc[j][0] = 0.f; acc[j][1] = 0.f; acc[j][2] = 0.f; acc[j][3] = 0.f;
        }

        #pragma unroll
        for (int kc = 0; kc < 32; kc += 8) {
            uint32_t a0 = Qs[row_l    ][kc + qd];
            uint32_t a1 = Qs[row_l + 8][kc + qd];
            uint32_t a2 = Qs[row_l    ][kc + qd + 4];
            uint32_t a3 = Qs[row_l + 8][kc + qd + 4];
            #pragma unroll
            for (int j = 0; j < 16; j++) {
                uint32_t b0 = Ks[buf][j*8 + g][kc + qd];
                uint32_t b1 = Ks[buf][j*8 + g][kc + qd + 4];
                mma_tf32(acc[j][0], acc[j][1], acc[j][2], acc[j][3],
                         a0, a1, a2, a3, b0, b1);
            }
        }

        uint32_t* Pb = g_P + (((size_t)bh * NN + r0) * NN + c0) / 2;
        #pragma unroll
        for (int j = 0; j < 16; j++) {
            int colp = j*4 + qd;
            float e0 = __expf(acc[j][0]);
            float e1 = __expf(acc[j][1]);
            float e2 = __expf(acc[j][2]);
            float e3 = __expf(acc[j][3]);
            __stcs(Pb + (size_t)(row_l    ) * (NN/2) + colp, pack_bf16(e0, e1));
            __stcs(Pb + (size_t)(row_l + 8) * (NN/2) + colp, pack_bf16(e2, e3));
            rs_lo += e0 + e1;
            rs_hi += e2 + e3;
        }
        __syncthreads();
    }

    rs_lo += __shfl_xor_sync(0xffffffffu, rs_lo, 1);
    rs_lo += __shfl_xor_sync(0xffffffffu, rs_lo, 2);
    rs_hi += __shfl_xor_sync(0xffffffffu, rs_hi, 1);
    rs_hi += __shfl_xor_sync(0xffffffffu, rs_hi, 2);
    if (qd == 0) {
        g_rowsum[bh * NN + r0 + row_l]     = rs_lo;
        g_rowsum[bh * NN + r0 + row_l + 8] = rs_hi;
    }
}

// ============================================================
// Kernel 3: t_out = diag(1/rowsum) * P * t_in ; g_acc += c_k * t_out
// bf16 mma, 3-stage cp.async ring over 32-wide m-chunks,
// ONE barrier per iteration. smem 38.4 KB -> 5 CTAs/SM.
// grid (16 row-tiles of 128, 32 bh), block 256 (8 warps).
// ============================================================
__global__ void pass_kernel(const float* __restrict__ coeffs, int pass) {
    __shared__ uint32_t Ps[3][128][20];   // bf16 pairs; 32 m per chunk (16 u32/row)
    __shared__ uint32_t Ts[3][16][40];    // bf16 row-pairs of t chunk

    const float* tin  = (pass & 1) ? g_t0 : g_t1;
    float*       tout = (pass & 1) ? g_t1 : g_t0;

    const int bh = blockIdx.y;
    const int r0 = blockIdx.x * 128;
    const float c = coeffs[(bh & 7) * 4 + pass];

    const int tid  = threadIdx.x;
    const int warp = tid >> 5;
    const int lane = tid & 31;
    const int g  = lane >> 2;
    const int qd = lane & 3;

    float acc[4][4];
    #pragma unroll
    for (int j = 0; j < 4; j++) {
        acc[j][0]=0.f; acc[j][1]=0.f; acc[j][2]=0.f; acc[j][3]=0.f;
    }

    const uint32_t* Prow = g_P + ((size_t)bh * NN + r0) * (NN/2);
    const float* Tb = tin + (size_t)bh * NN * HD;
    const int row_l = warp * 16 + g;

    // prologue: async-load P chunks 0 and 1; stage t chunk 0
    for (int l = tid; l < 512; l += 256) {
        int r = l >> 2, mq = l & 3;
        uint32_t s = (uint32_t)__cvta_generic_to_shared(&Ps[0][r][mq*4]);
        cp16(s, Prow + (size_t)r * (NN/2) + mq*4);
    }
    asm volatile("cp.async.commit_group;");
    for (int l = tid; l < 512; l += 256) {
        int r = l >> 2, mq = l & 3;
        uint32_t s = (uint32_t)__cvta_generic_to_shared(&Ps[1][r][mq*4]);
        cp16(s, Prow + (size_t)r * (NN/2) + 16 + mq*4);
    }
    asm volatile("cp.async.commit_group;");
    if (tid < 128) {
        int m2 = tid >> 3, cq = tid & 7;
        float4 v0 = *(const float4*)(Tb + (size_t)(2*m2    ) * HD + cq * 4);
        float4 v1 = *(const float4*)(Tb + (size_t)(2*m2 + 1) * HD + cq * 4);
        Ts[0][m2][cq*4+0] = pack_bf16(v0.x, v1.x);
        Ts[0][m2][cq*4+1] = pack_bf16(v0.y, v1.y);
        Ts[0][m2][cq*4+2] = pack_bf16(v0.z, v1.z);
        Ts[0][m2][cq*4+3] = pack_bf16(v0.w, v1.w);
    }

    for (int i = 0; i < 64; i++) {
        const int buf = i % 3;

        if (i < 62) { asm volatile("cp.async.wait_group 1;"); }
        else        { asm volatile("cp.async.wait_group 0;"); }
        __syncthreads();
        // sync(i): all threads have finished MMA(i-1); safe to overwrite
        // Ps[(i+2)%3] (last read at MMA(i-1)) and Ts[(i+1)%3] (last read MMA(i-2)).

        if (i < 62) {
            const uint32_t* Pg = Prow + (i + 2) * 16;
            const int nb = (i + 2) % 3;
            for (int l = tid; l < 512; l += 256) {
                int r = l >> 2, mq = l & 3;
                uint32_t s = (uint32_t)__cvta_generic_to_shared(&Ps[nb][r][mq*4]);
                cp16(s, Pg + (size_t)r * (NN/2) + mq*4);
            }
            asm volatile("cp.async.commit_group;");
        }

        if (i < 63 && tid < 128) {
            const int nb = (i + 1) % 3;
            const int m0n = (i + 1) * 32;
            int m2 = tid >> 3, cq = tid & 7;
            float4 v0 = *(const float4*)(Tb + (size_t)(m0n + 2*m2    ) * HD + cq * 4);
            float4 v1 = *(const float4*)(Tb + (size_t)(m0n + 2*m2 + 1) * HD + cq * 4);
            Ts[nb][m2][cq*4+0] = pack_bf16(v0.x, v1.x);
            Ts[nb][m2][cq*4+1] = pack_bf16(v0.y, v1.y);
            Ts[nb][m2][cq*4+2] = pack_bf16(v0.z, v1.z);
            Ts[nb][m2][cq*4+3] = pack_bf16(v0.w, v1.w);
        }

        #pragma unroll
        for (int kc = 0; kc < 16; kc += 8) {
            uint32_t a0 = Ps[buf][row_l    ][kc + qd];
            uint32_t a1 = Ps[buf][row_l + 8][kc + qd];
            uint32_t a2 = Ps[buf][row_l    ][kc + qd + 4];
            uint32_t a3 = Ps[buf][row_l + 8][kc + qd + 4];
            #pragma unroll
            for (int j = 0; j < 4; j++) {
                uint32_t b0 = Ts[buf][kc + qd    ][j*8 + g];
                uint32_t b1 = Ts[buf][kc + qd + 4][j*8 + g];
                mma_bf16(acc[j][0], acc[j][1], acc[j][2], acc[j][3],
                         a0, a1, a2, a3, b0, b1);
            }
        }
    }

    const int r_lo = r0 + row_l;
    const int r_hi = r_lo + 8;
    const float inv_lo = 1.0f / g_rowsum[bh * NN + r_lo];
    const float inv_hi = 1.0f / g_rowsum[bh * NN + r_hi];
    #pragma unroll
    for (int j = 0; j < 4; j++) {
        int col = j*8 + qd*2;
        size_t o_lo = ((size_t)bh * NN + r_lo) * HD + col;
        size_t o_hi = ((size_t)bh * NN + r_hi) * HD + col;
        float2 lo = make_float2(acc[j][0] * inv_lo, acc[j][1] * inv_lo);
        float2 hi = make_float2(acc[j][2] * inv_hi, acc[j][3] * inv_hi);
        if (pass != 3) {
            *(float2*)(tout + o_lo) = lo;
            *(float2*)(tout + o_hi) = hi;
        }
        float2 a_lo = *(float2*)(g_acc + o_lo);
        float2 a_hi = *(float2*)(g_acc + o_hi);
        a_lo.x += c * lo.x; a_lo.y += c * lo.y;
        a_hi.x += c * hi.x; a_hi.y += c * hi.y;
        *(float2*)(g_acc + o_lo) = a_lo;
        *(float2*)(g_acc + o_hi) = a_hi;
    }
}

// ============================================================
// Kernel 4: out = merged(g_acc) @ Wo + bo, 3xTF32 tensor path.
// grid (64, 4): 128-row x 64-col tiles.
// ============================================================
__global__ void outproj_kernel(const float* __restrict__ Wo,
                               const float* __restrict__ bo,
                               float* __restrict__ out) {
    const int m0 = blockIdx.x * 128;
    const int c0 = blockIdx.y * 64;

    __shared__ uint32_t MsH[128][36];
    __shared__ uint32_t MsL[128][36];
    __shared__ uint32_t WtH[64][36];
    __shared__ uint32_t WtL[64][36];

    const int tid  = threadIdx.x;
    const int warp = tid >> 5;
    const int lane = tid & 31;
    const int g  = lane >> 2;
    const int qd = lane & 3;
    const int row_l = warp * 16 + g;

    float acc[8][4];
    #pragma unroll
    for (int j = 0; j < 8; j++) {
        acc[j][0]=0.f; acc[j][1]=0.f; acc[j][2]=0.f; acc[j][3]=0.f;
    }

    for (int k0 = 0; k0 < DD; k0 += 32) {
        const int hh = k0 >> 5;                 // one head per 32-wide k tile
        for (int l = tid; l < 1024; l += 256) {
            int r = l >> 3, kq = l & 7;
            int m = m0 + r;
            int b_ = m >> 11, n = m & 2047;
            float4 v = *(const float4*)(g_acc + ((size_t)(b_ * HH + hh) * NN + n) * HD + kq * 4);
            uint32_t hx = f2tf(v.x), hy = f2tf(v.y), hz = f2tf(v.z), hw = f2tf(v.w);
            MsH[r][kq*4+0] = hx; MsH[r][kq*4+1] = hy;
            MsH[r][kq*4+2] = hz; MsH[r][kq*4+3] = hw;
            MsL[r][kq*4+0] = f2tf(v.x - __uint_as_float(hx));
            MsL[r][kq*4+1] = f2tf(v.y - __uint_as_float(hy));
            MsL[r][kq*4+2] = f2tf(v.z - __uint_as_float(hz));
            MsL[r][kq*4+3] = f2tf(v.w - __uint_as_float(hw));
        }
        for (int l = tid; l < 2048; l += 256) {
            int c = l & 63, k = l >> 6;
            float w = Wo[(size_t)(k0 + k) * DD + c0 + c];
            uint32_t h = f2tf(w);
            WtH[c][k] = h;
            WtL[c][k] = f2tf(w - __uint_as_float(h));
        }
        __syncthreads();

        #pragma unroll
        for (int kc = 0; kc < 32; kc += 8) {
            uint32_t aH0 = MsH[row_l    ][kc + qd];
            uint32_t aH1 = MsH[row_l + 8][kc + qd];
            uint32_t aH2 = MsH[row_l    ][kc + qd + 4];
            uint32_t aH3 = MsH[row_l + 8][kc + qd + 4];
            uint32_t aL0 = MsL[row_l    ][kc + qd];
            uint32_t aL1 = MsL[row_l + 8][kc + qd];
            uint32_t aL2 = MsL[row_l    ][kc + qd + 4];
            uint32_t aL3 = MsL[row_l + 8][kc + qd + 4];
            #pragma unroll
            for (int j = 0; j < 8; j++) {
                uint32_t bH0 = WtH[j*8 + g][kc + qd];
                uint32_t bH1 = WtH[j*8 + g][kc + qd + 4];
                uint32_t bL0 = WtL[j*8 + g][kc + qd];
                uint32_t bL1 = WtL[j*8 + g][kc + qd + 4];
                mma_tf32(acc[j][0], acc[j][1], acc[j][2], acc[j][3],
                         aH0, aH1, aH2, aH3, bH0, bH1);
                mma_tf32(acc[j][0], acc[j][1], acc[j][2], acc[j][3],
                         aH0, aH1, aH2, aH3, bL0, bL1);
                mma_tf32(acc[j][0], acc[j][1], acc[j][2], acc[j][3],
                         aL0, aL1, aL2, aL3, bH0, bH1);
            }
        }
        __syncthreads();
    }

    #pragma unroll
    for (int j = 0; j < 8; j++) {
        #pragma unroll
        for (int half = 0; half < 2; half++) {
            int m = m0 + row_l + half * 8;
            #pragma unroll
            for (int p = 0; p < 2; p++) {
                int c = c0 + j*8 + qd*2 + p;
                out[(size_t)m * DD + c] = acc[j][half*2 + p] + bo[c];
            }
        }
    }
}

// ============================================================
extern "C" void kernel_launch(void* const* d_in, const int* in_sizes, int n_in,
                              void* d_out, int out_size) {
    const float* x      = (const float*)d_in[0];
    const float* Wq     = (const float*)d_in[1];
    const float* bq     = (const float*)d_in[2];
    const float* Wk     = (const float*)d_in[3];
    const float* bk     = (const float*)d_in[4];
    const float* Wv     = (const float*)d_in[5];
    const float* bv     = (const float*)d_in[6];
    const float* Wo     = (const float*)d_in[7];
    const float* bo     = (const float*)d_in[8];
    const float* coeffs = (const float*)d_in[9];
    float* out = (float*)d_out;

    dim3 g1(64, 4, 3);
    qkv_kernel<<<g1, 256>>>(x, Wq, bq, Wk, bk, Wv, bv, coeffs);

    dim3 g2(16, 32);
    attnP_kernel<<<g2, 256>>>();

    pass_kernel<<<g2, 256>>>(coeffs, 1);
    pass_kernel<<<g2, 256>>>(coeffs, 2);
    pass_kernel<<<g2, 256>>>(coeffs, 3);

    dim3 g4(64, 4);
    outproj_kernel<<<g4, 256>>>(Wo, bo, out);
}

// round 15
// speedup vs baseline: 1.5635x; 1.5635x over previous
#include <cuda_runtime.h>
#include <math.h>
#include <stdint.h>

#define HH 8
#define HD 32
#define BB 4
#define NN 2048
#define DD 256
#define BH (BB*HH)   // 32

// ---- device scratch (static: allocation-free rule) ----
__device__ float g_Q[(size_t)BH*NN*HD];
__device__ float g_K[(size_t)BH*NN*HD];
__device__ uint32_t g_P[(size_t)BH*NN*NN/2];       // bf16 pairs, 256 MB
__device__ float g_rowsum[BH*NN];
__device__ uint32_t g_tb0[(size_t)BH*(NN/2)*HD];   // t as bf16 row-pairs: [bh][m2][col]
__device__ uint32_t g_tb1[(size_t)BH*(NN/2)*HD];
__device__ float g_acc[(size_t)BH*NN*HD];

__device__ __forceinline__ uint32_t f2tf(float f) {
    uint32_t r;
    asm("cvt.rna.tf32.f32 %0, %1;" : "=r"(r) : "f"(f));
    return r;
}

// pack two fp32 -> bf16x2 (lo in low half, hi in high half)
__device__ __forceinline__ uint32_t pack_bf16(float lo, float hi) {
    uint32_t r;
    asm("cvt.rn.bf16x2.f32 %0, %1, %2;" : "=r"(r) : "f"(hi), "f"(lo));
    return r;
}

__device__ __forceinline__ void mma_tf32(float& d0, float& d1, float& d2, float& d3,
                                         uint32_t a0, uint32_t a1, uint32_t a2, uint32_t a3,
                                         uint32_t b0, uint32_t b1) {
    asm("mma.sync.aligned.m16n8k8.row.col.f32.tf32.tf32.f32 "
        "{%0,%1,%2,%3},{%4,%5,%6,%7},{%8,%9},{%0,%1,%2,%3};"
        : "+f"(d0), "+f"(d1), "+f"(d2), "+f"(d3)
        : "r"(a0), "r"(a1), "r"(a2), "r"(a3), "r"(b0), "r"(b1));
}

__device__ __forceinline__ void mma_bf16(float& d0, float& d1, float& d2, float& d3,
                                         uint32_t a0, uint32_t a1, uint32_t a2, uint32_t a3,
                                         uint32_t b0, uint32_t b1) {
    asm("mma.sync.aligned.m16n8k16.row.col.f32.bf16.bf16.f32 "
        "{%0,%1,%2,%3},{%4,%5,%6,%7},{%8,%9},{%0,%1,%2,%3};"
        : "+f"(d0), "+f"(d1), "+f"(d2), "+f"(d3)
        : "r"(a0), "r"(a1), "r"(a2), "r"(a3), "r"(b0), "r"(b1));
}

__device__ __forceinline__ void cp16(uint32_t saddr, const void* gptr) {
    asm volatile("cp.async.cg.shared.global [%0], [%1], 16;" :: "r"(saddr), "l"(gptr));
}

// ============================================================
// Kernel 1: QKV projection + head split, 3xTF32 tensor path.
// grid (64, 4, 3): 128-row x 64-col tiles, z = which matrix.
// mat==2 (V): writes g_acc = c0*v and v as bf16 row-pairs to g_tb0.
// ============================================================
__global__ void qkv_kernel(const float* __restrict__ x,
                           const float* __restrict__ Wq, const float* __restrict__ bq,
                           const float* __restrict__ Wk, const float* __restrict__ bk,
                           const float* __restrict__ Wv, const float* __restrict__ bv,
                           const float* __restrict__ coeffs) {
    const int mat = blockIdx.z;
    const float* W    = (mat == 0) ? Wq : ((mat == 1) ? Wk : Wv);
    const float* bias = (mat == 0) ? bq : ((mat == 1) ? bk : bv);
    const int m0 = blockIdx.x * 128;
    const int c0 = blockIdx.y * 64;

    __shared__ uint32_t XsH[128][36];
    __shared__ uint32_t XsL[128][36];
    __shared__ uint32_t WtH[64][36];
    __shared__ uint32_t WtL[64][36];

    const int tid  = threadIdx.x;
    const int warp = tid >> 5;
    const int lane = tid & 31;
    const int g  = lane >> 2;
    const int qd = lane & 3;
    const int row_l = warp * 16 + g;

    float acc[8][4];
    #pragma unroll
    for (int j = 0; j < 8; j++) {
        acc[j][0]=0.f; acc[j][1]=0.f; acc[j][2]=0.f; acc[j][3]=0.f;
    }

    for (int k0 = 0; k0 < DD; k0 += 32) {
        for (int l = tid; l < 1024; l += 256) {
            int r = l >> 3, kq = l & 7;
            float4 v = *(const float4*)(x + (size_t)(m0 + r) * DD + k0 + kq * 4);
            uint32_t hx = f2tf(v.x), hy = f2tf(v.y), hz = f2tf(v.z), hw = f2tf(v.w);
            XsH[r][kq*4+0] = hx; XsH[r][kq*4+1] = hy;
            XsH[r][kq*4+2] = hz; XsH[r][kq*4+3] = hw;
            XsL[r][kq*4+0] = f2tf(v.x - __uint_as_float(hx));
            XsL[r][kq*4+1] = f2tf(v.y - __uint_as_float(hy));
            XsL[r][kq*4+2] = f2tf(v.z - __uint_as_float(hz));
            XsL[r][kq*4+3] = f2tf(v.w - __uint_as_float(hw));
        }
        for (int l = tid; l < 2048; l += 256) {
            int c = l & 63, k = l >> 6;
            float w = W[(size_t)(k0 + k) * DD + c0 + c];
            uint32_t h = f2tf(w);
            WtH[c][k] = h;
            WtL[c][k] = f2tf(w - __uint_as_float(h));
        }
        __syncthreads();

        #pragma unroll
        for (int kc = 0; kc < 32; kc += 8) {
            uint32_t aH0 = XsH[row_l    ][kc + qd];
            uint32_t aH1 = XsH[row_l + 8][kc + qd];
            uint32_t aH2 = XsH[row_l    ][kc + qd + 4];
            uint32_t aH3 = XsH[row_l + 8][kc + qd + 4];
            uint32_t aL0 = XsL[row_l    ][kc + qd];
            uint32_t aL1 = XsL[row_l + 8][kc + qd];
            uint32_t aL2 = XsL[row_l    ][kc + qd + 4];
            uint32_t aL3 = XsL[row_l + 8][kc + qd + 4];
            #pragma unroll
            for (int j = 0; j < 8; j++) {
                uint32_t bH0 = WtH[j*8 + g][kc + qd];
                uint32_t bH1 = WtH[j*8 + g][kc + qd + 4];
                uint32_t bL0 = WtL[j*8 + g][kc + qd];
                uint32_t bL1 = WtL[j*8 + g][kc + qd + 4];
                mma_tf32(acc[j][0], acc[j][1], acc[j][2], acc[j][3],
                         aH0, aH1, aH2, aH3, bH0, bH1);
                mma_tf32(acc[j][0], acc[j][1], acc[j][2], acc[j][3],
                         aH0, aH1, aH2, aH3, bL0, bL1);
                mma_tf32(acc[j][0], acc[j][1], acc[j][2], acc[j][3],
                         aL0, aL1, aL2, aL3, bH0, bH1);
            }
        }
        __syncthreads();
    }

    #pragma unroll
    for (int j = 0; j < 8; j++) {
        #pragma unroll
        for (int half = 0; half < 2; half++) {
            int m = m0 + row_l + half * 8;
            int b_ = m >> 11, n = m & 2047;
            int cbase = c0 + j*8 + qd*2;           // even -> both cols in same head
            int hh = cbase >> 5, d0 = cbase & 31;
            float v0 = acc[j][half*2 + 0] + bias[cbase];
            float v1 = acc[j][half*2 + 1] + bias[cbase + 1];
            size_t idx = ((size_t)(b_ * HH + hh) * NN + n) * HD + d0;
            if (mat == 0) {
                g_Q[idx] = v0; g_Q[idx + 1] = v1;
            } else if (mat == 1) {
                g_K[idx] = v0; g_K[idx + 1] = v1;
            } else {
                float cc = coeffs[hh * 4];
                g_acc[idx]     = cc * v0;
                g_acc[idx + 1] = cc * v1;
                // pack v rows (2e, 2e+1) -> bf16 pairs (lanes g even/odd exchange)
                float o0 = __shfl_xor_sync(0xffffffffu, v0, 4);
                float o1 = __shfl_xor_sync(0xffffffffu, v1, 4);
                if ((g & 1) == 0) {
                    size_t tix = ((size_t)(b_ * HH + hh) * (NN/2) + (n >> 1)) * HD + d0;
                    g_tb0[tix]     = pack_bf16(v0, o0);
                    g_tb0[tix + 1] = pack_bf16(v1, o1);
                }
            }
        }
    }
}

// ============================================================
// Kernel 2: P = exp(Q K^T * scale) -> bf16 + rowsums.
// cp.async double-buffered K staging; K fed as raw fp32 (tf32-truncated).
// grid (16 row-tiles of 128, 32 bh), block 256 (8 warps).  [R12 version]
// ============================================================
__global__ void attnP_kernel() {
    const int bh = blockIdx.y;
    const int r0 = blockIdx.x * 128;

    __shared__ uint32_t Qs[128][36];      // tf32 (rna), scale folded
    __shared__ uint32_t Ks[2][128][36];   // raw fp32 bits via cp.async

    const int tid  = threadIdx.x;
    const int warp = tid >> 5;
    const int lane = tid & 31;
    const int g  = lane >> 2;   // 0..7
    const int qd = lane & 3;    // 0..3

    const float scale = 0.17677669529663687f;  // 1/sqrt(32), folded into Q

    const float* Qb = g_Q + ((size_t)bh * NN + r0) * HD;
    const float* Kb = g_K + (size_t)bh * NN * HD;

    for (int l = tid; l < 1024; l += 256) {
        int r = l >> 3, kq = l & 7;
        uint32_t s = (uint32_t)__cvta_generic_to_shared(&Ks[0][r][kq*4]);
        cp16(s, Kb + (size_t)r * HD + kq * 4);
    }
    asm volatile("cp.async.commit_group;");

    for (int l = tid; l < 1024; l += 256) {
        int r = l >> 3, kq = l & 7;
        float4 v = *(const float4*)(Qb + (size_t)r * HD + kq * 4);
        uint4 u;
        u.x = f2tf(v.x * scale); u.y = f2tf(v.y * scale);
        u.z = f2tf(v.z * scale); u.w = f2tf(v.w * scale);
        *(uint4*)&Qs[r][kq*4] = u;
    }

    const int row_l = warp * 16 + g;
    float rs_lo = 0.f, rs_hi = 0.f;

    for (int ct = 0; ct < 16; ct++) {
        const int c0 = ct * 128;
        const int buf = ct & 1;

        if (ct < 15) {
            const float* Kn = Kb + (size_t)(c0 + 128) * HD;
            for (int l = tid; l < 1024; l += 256) {
                int r = l >> 3, kq = l & 7;
                uint32_t s = (uint32_t)__cvta_generic_to_shared(&Ks[buf^1][r][kq*4]);
                cp16(s, Kn + (size_t)r * HD + kq * 4);
            }
            asm volatile("cp.async.commit_group;");
        }

        if (ct < 15) { asm volatile("cp.async.wait_group 1;"); }
        else         { asm volatile("cp.async.wait_group 0;"); }
        __syncthreads();

        float acc[16][4];
        #pragma unroll
        for (int j = 0; j < 16; j++) {
            acc[j][0] = 0.f; acc[j][1] = 0.f; acc[j][2] = 0.f; acc[j][3] = 0.f;
        }

        #pragma unroll
        for (int kc = 0; kc < 32; kc += 8) {
            uint32_t a0 = Qs[row_l    ][kc + qd];
            uint32_t a1 = Qs[row_l + 8][kc + qd];
            uint32_t a2 = Qs[row_l    ][kc + qd + 4];
            uint32_t a3 = Qs[row_l + 8][kc + qd + 4];
            #pragma unroll
            for (int j = 0; j < 16; j++) {
                uint32_t b0 = Ks[buf][j*8 + g][kc + qd];
                uint32_t b1 = Ks[buf][j*8 + g][kc + qd + 4];
                mma_tf32(acc[j][0], acc[j][1], acc[j][2], acc[j][3],
                         a0, a1, a2, a3, b0, b1);
            }
        }

        uint32_t* Pb = g_P + (((size_t)bh * NN + r0) * NN + c0) / 2;
        #pragma unroll
        for (int j = 0; j < 16; j++) {
            int colp = j*4 + qd;
            float e0 = __expf(acc[j][0]);
            float e1 = __expf(acc[j][1]);
            float e2 = __expf(acc[j][2]);
            float e3 = __expf(acc[j][3]);
            __stcs(Pb + (size_t)(row_l    ) * (NN/2) + colp, pack_bf16(e0, e1));
            __stcs(Pb + (size_t)(row_l + 8) * (NN/2) + colp, pack_bf16(e2, e3));
            rs_lo += e0 + e1;
            rs_hi += e2 + e3;
        }
        __syncthreads();
    }

    rs_lo += __shfl_xor_sync(0xffffffffu, rs_lo, 1);
    rs_lo += __shfl_xor_sync(0xffffffffu, rs_lo, 2);
    rs_hi += __shfl_xor_sync(0xffffffffu, rs_hi, 1);
    rs_hi += __shfl_xor_sync(0xffffffffu, rs_hi, 2);
    if (qd == 0) {
        g_rowsum[bh * NN + r0 + row_l]     = rs_lo;
        g_rowsum[bh * NN + r0 + row_l + 8] = rs_hi;
    }
}

// ============================================================
// Kernel 3: t_out = diag(1/rowsum) * P * t_in ; g_acc += c_k * t_out
// bf16 mma, cp.async double-buffered over 64-wide m-chunks.
// t comes pre-packed bf16 (g_tb*) -> staging is pure cp.async
// in the SAME commit group as the P chunk.
// grid (16 row-tiles of 128, 32 bh), block 256 (8 warps).
// ============================================================
__global__ void pass_kernel(const float* __restrict__ coeffs, int pass) {
    __shared__ uint32_t Ps[2][128][36];   // bf16 pairs; 64 m per chunk
    __shared__ uint32_t Ts[2][32][40];    // bf16 row-pairs of t chunk

    const uint32_t* tbin  = (pass & 1) ? g_tb0 : g_tb1;
    uint32_t*       tbout = (pass & 1) ? g_tb1 : g_tb0;

    const int bh = blockIdx.y;
    const int r0 = blockIdx.x * 128;
    const float c = coeffs[(bh & 7) * 4 + pass];

    const int tid  = threadIdx.x;
    const int warp = tid >> 5;
    const int lane = tid & 31;
    const int g  = lane >> 2;
    const int qd = lane & 3;

    float acc[4][4];
    #pragma unroll
    for (int j = 0; j < 4; j++) {
        acc[j][0]=0.f; acc[j][1]=0.f; acc[j][2]=0.f; acc[j][3]=0.f;
    }

    const uint32_t* Prow = g_P + ((size_t)bh * NN + r0) * (NN/2);
    const uint32_t* Tbb  = tbin + (size_t)bh * (NN/2) * HD;
    const int row_l = warp * 16 + g;

    // prologue: async-load P chunk 0 + t chunk 0 as one group
    for (int l = tid; l < 1024; l += 256) {
        int r = l >> 3, mq = l & 7;
        uint32_t s = (uint32_t)__cvta_generic_to_shared(&Ps[0][r][mq*4]);
        cp16(s, Prow + (size_t)r * (NN/2) + mq*4);
    }
    {
        int m2 = tid >> 3, mq = tid & 7;
        uint32_t s = (uint32_t)__cvta_generic_to_shared(&Ts[0][m2][mq*4]);
        cp16(s, Tbb + (size_t)m2 * HD + mq*4);
    }
    asm volatile("cp.async.commit_group;");

    for (int i = 0; i < 32; i++) {
        const int buf = i & 1;

        // issue async load of next P + t chunk into the other buffer
        if (i < 31) {
            const uint32_t* Pg = Prow + (i + 1) * 32;
            for (int l = tid; l < 1024; l += 256) {
                int r = l >> 3, mq = l & 7;
                uint32_t s = (uint32_t)__cvta_generic_to_shared(&Ps[buf^1][r][mq*4]);
                cp16(s, Pg + (size_t)r * (NN/2) + mq*4);
            }
            const uint32_t* Tg = Tbb + (size_t)(i + 1) * 32 * HD;
            {
                int m2 = tid >> 3, mq = tid & 7;
                uint32_t s = (uint32_t)__cvta_generic_to_shared(&Ts[buf^1][m2][mq*4]);
                cp16(s, Tg + (size_t)m2 * HD + mq*4);
            }
            asm volatile("cp.async.commit_group;");
        }

        if (i < 31) { asm volatile("cp.async.wait_group 1;"); }
        else        { asm volatile("cp.async.wait_group 0;"); }
        __syncthreads();

        #pragma unroll
        for (int kc = 0; kc < 32; kc += 8) {
            uint32_t a0 = Ps[buf][row_l    ][kc + qd];
            uint32_t a1 = Ps[buf][row_l + 8][kc + qd];
            uint32_t a2 = Ps[buf][row_l    ][kc + qd + 4];
            uint32_t a3 = Ps[buf][row_l + 8][kc + qd + 4];
            #pragma unroll
            for (int j = 0; j < 4; j++) {
                uint32_t b0 = Ts[buf][kc + qd    ][j*8 + g];
                uint32_t b1 = Ts[buf][kc + qd + 4][j*8 + g];
                mma_bf16(acc[j][0], acc[j][1], acc[j][2], acc[j][3],
                         a0, a1, a2, a3, b0, b1);
            }
        }
        __syncthreads();
    }

    const int r_lo = r0 + row_l;
    const int r_hi = r_lo + 8;
    const float inv_lo = 1.0f / g_rowsum[bh * NN + r_lo];
    const float inv_hi = 1.0f / g_rowsum[bh * NN + r_hi];
    #pragma unroll
    for (int j = 0; j < 4; j++) {
        int col = j*8 + qd*2;
        size_t o_lo = ((size_t)bh * NN + r_lo) * HD + col;
        size_t o_hi = ((size_t)bh * NN + r_hi) * HD + col;
        float2 lo = make_float2(acc[j][0] * inv_lo, acc[j][1] * inv_lo);
        float2 hi = make_float2(acc[j][2] * inv_hi, acc[j][3] * inv_hi);
        // g_acc RMW (fp32, exact)
        float2 a_lo = *(float2*)(g_acc + o_lo);
        float2 a_hi = *(float2*)(g_acc + o_hi);
        a_lo.x += c * lo.x; a_lo.y += c * lo.y;
        a_hi.x += c * hi.x; a_hi.y += c * hi.y;
        *(float2*)(g_acc + o_lo) = a_lo;
        *(float2*)(g_acc + o_hi) = a_hi;
        // t_out as bf16 row-pairs (skip on final pass)
        if (pass != 3) {
            float olx = __shfl_xor_sync(0xffffffffu, lo.x, 4);
            float oly = __shfl_xor_sync(0xffffffffu, lo.y, 4);
            float ohx = __shfl_xor_sync(0xffffffffu, hi.x, 4);
            float ohy = __shfl_xor_sync(0xffffffffu, hi.y, 4);
            if ((g & 1) == 0) {
                size_t t_lo = ((size_t)bh * (NN/2) + (r_lo >> 1)) * HD + col;
                size_t t_hi = ((size_t)bh * (NN/2) + (r_hi >> 1)) * HD + col;
                tbout[t_lo]     = pack_bf16(lo.x, olx);
                tbout[t_lo + 1] = pack_bf16(lo.y, oly);
                tbout[t_hi]     = pack_bf16(hi.x, ohx);
                tbout[t_hi + 1] = pack_bf16(hi.y, ohy);
            }
        }
    }
}

// ============================================================
// Kernel 4: out = merged(g_acc) @ Wo + bo  (scalar fp32 — small)
// grid (128, 4), block 256.  [R12 version]
// ============================================================
__global__ void outproj_kernel(const float* __restrict__ Wo,
                               const float* __restrict__ bo,
                               float* __restrict__ out) {
    const int m0 = blockIdx.x * 64;
    const int c0 = blockIdx.y * 64;

    __shared__ float Ms[64][33];
    __shared__ float Ws[32][64];

    const int tid = threadIdx.x;
    const int ty = tid >> 4, tx = tid & 15;

    float acc[4][4] = {};

    for (int k0 = 0; k0 < DD; k0 += 32) {
        int hh = k0 >> 5;
        for (int l = tid; l < 512; l += 256) {
            int r = l >> 3, kq = l & 7;
            int m = m0 + r;
            int b_ = m >> 11, n = m & 2047;
            float4 v = *(const float4*)(g_acc + ((size_t)(b_ * HH + hh) * NN + n) * HD + kq * 4);
            Ms[r][kq*4+0] = v.x; Ms[r][kq*4+1] = v.y;
            Ms[r][kq*4+2] = v.z; Ms[r][kq*4+3] = v.w;
        }
        for (int l = tid; l < 512; l += 256) {
            int k = l >> 4, cq = l & 15;
            *(float4*)&Ws[k][cq*4] = *(const float4*)(Wo + (size_t)(k0 + k) * DD + c0 + cq * 4);
        }
        __syncthreads();
        #pragma unroll
        for (int kk = 0; kk < 32; kk++) {
            float a0 = Ms[ty*4+0][kk];
            float a1 = Ms[ty*4+1][kk];
            float a2 = Ms[ty*4+2][kk];
            float a3 = Ms[ty*4+3][kk];
            float4 b = *(float4*)&Ws[kk][tx*4];
            acc[0][0] += a0*b.x; acc[0][1] += a0*b.y; acc[0][2] += a0*b.z; acc[0][3] += a0*b.w;
            acc[1][0] += a1*b.x; acc[1][1] += a1*b.y; acc[1][2] += a1*b.z; acc[1][3] += a1*b.w;
            acc[2][0] += a2*b.x; acc[2][1] += a2*b.y; acc[2][2] += a2*b.z; acc[2][3] += a2*b.w;
            acc[3][0] += a3*b.x; acc[3][1] += a3*b.y; acc[3][2] += a3*b.z; acc[3][3] += a3*b.w;
        }
        __syncthreads();
    }

    #pragma unroll
    for (int i = 0; i < 4; i++) {
        int m = m0 + ty * 4 + i;
        #pragma unroll
        for (int j = 0; j < 4; j++) {
            int cc = c0 + tx * 4 + j;
            out[(size_t)m * DD + cc] = acc[i][j] + bo[cc];
        }
    }
}

// ============================================================
extern "C" void kernel_launch(void* const* d_in, const int* in_sizes, int n_in,
                              void* d_out, int out_size) {
    const float* x      = (const float*)d_in[0];
    const float* Wq     = (const float*)d_in[1];
    const float* bq     = (const float*)d_in[2];
    const float* Wk     = (const float*)d_in[3];
    const float* bk     = (const float*)d_in[4];
    const float* Wv     = (const float*)d_in[5];
    const float* bv     = (const float*)d_in[6];
    const float* Wo     = (const float*)d_in[7];
    const float* bo     = (const float*)d_in[8];
    const float* coeffs = (const float*)d_in[9];
    float* out = (float*)d_out;

    dim3 g1(64, 4, 3);
    qkv_kernel<<<g1, 256>>>(x, Wq, bq, Wk, bk, Wv, bv, coeffs);

    dim3 g2(16, 32);
    attnP_kernel<<<g2, 256>>>();

    pass_kernel<<<g2, 256>>>(coeffs, 1);
    pass_kernel<<<g2, 256>>>(coeffs, 2);
    pass_kernel<<<g2, 256>>>(coeffs, 3);

    dim3 g4(128, 4);
    outproj_kernel<<<g4, 256>>>(Wo, bo, out);
}

// round 17
// speedup vs baseline: 1.6276x; 1.0410x over previous
#include <cuda_runtime.h>
#include <math.h>
#include <stdint.h>

#define HH 8
#define HD 32
#define BB 4
#define NN 2048
#define DD 256
#define BH (BB*HH)   // 32

// ---- device scratch (static: allocation-free rule) ----
__device__ float g_Q[(size_t)BH*NN*HD];
__device__ float g_K[(size_t)BH*NN*HD];
// P stored as bf16 pairs, permuted within each 32-pair sub-block:
// original pair-col c = 4*jl + qd  ->  stored offset qd*8 + jl
__device__ uint32_t g_P[(size_t)BH*NN*NN/2];       // 256 MB
__device__ float g_rowsum[BH*NN];
__device__ uint32_t g_tb0[(size_t)BH*(NN/2)*HD];   // t as bf16 row-pairs: [bh][m2][col]
__device__ uint32_t g_tb1[(size_t)BH*(NN/2)*HD];
__device__ float g_acc[(size_t)BH*NN*HD];

__device__ __forceinline__ uint32_t f2tf(float f) {
    uint32_t r;
    asm("cvt.rna.tf32.f32 %0, %1;" : "=r"(r) : "f"(f));
    return r;
}

// pack two fp32 -> bf16x2 (lo in low half, hi in high half)
__device__ __forceinline__ uint32_t pack_bf16(float lo, float hi) {
    uint32_t r;
    asm("cvt.rn.bf16x2.f32 %0, %1, %2;" : "=r"(r) : "f"(hi), "f"(lo));
    return r;
}

__device__ __forceinline__ void mma_tf32(float& d0, float& d1, float& d2, float& d3,
                                         uint32_t a0, uint32_t a1, uint32_t a2, uint32_t a3,
                                         uint32_t b0, uint32_t b1) {
    asm("mma.sync.aligned.m16n8k8.row.col.f32.tf32.tf32.f32 "
        "{%0,%1,%2,%3},{%4,%5,%6,%7},{%8,%9},{%0,%1,%2,%3};"
        : "+f"(d0), "+f"(d1), "+f"(d2), "+f"(d3)
        : "r"(a0), "r"(a1), "r"(a2), "r"(a3), "r"(b0), "r"(b1));
}

__device__ __forceinline__ void mma_bf16(float& d0, float& d1, float& d2, float& d3,
                                         uint32_t a0, uint32_t a1, uint32_t a2, uint32_t a3,
                                         uint32_t b0, uint32_t b1) {
    asm("mma.sync.aligned.m16n8k16.row.col.f32.bf16.bf16.f32 "
        "{%0,%1,%2,%3},{%4,%5,%6,%7},{%8,%9},{%0,%1,%2,%3};"
        : "+f"(d0), "+f"(d1), "+f"(d2), "+f"(d3)
        : "r"(a0), "r"(a1), "r"(a2), "r"(a3), "r"(b0), "r"(b1));
}

__device__ __forceinline__ void cp16(uint32_t saddr, const void* gptr) {
    asm volatile("cp.async.cg.shared.global [%0], [%1], 16;" :: "r"(saddr), "l"(gptr));
}

// ============================================================
// Kernel 1: QKV projection + head split, 3xTF32 tensor path.
// grid (64, 4, 3): 128-row x 64-col tiles, z = which matrix.
// mat==2 (V): writes g_acc = c0*v and v as bf16 row-pairs to g_tb0.
// ============================================================
__global__ void qkv_kernel(const float* __restrict__ x,
                           const float* __restrict__ Wq, const float* __restrict__ bq,
                           const float* __restrict__ Wk, const float* __restrict__ bk,
                           const float* __restrict__ Wv, const float* __restrict__ bv,
                           const float* __restrict__ coeffs) {
    const int mat = blockIdx.z;
    const float* W    = (mat == 0) ? Wq : ((mat == 1) ? Wk : Wv);
    const float* bias = (mat == 0) ? bq : ((mat == 1) ? bk : bv);
    const int m0 = blockIdx.x * 128;
    const int c0 = blockIdx.y * 64;

    __shared__ uint32_t XsH[128][36];
    __shared__ uint32_t XsL[128][36];
    __shared__ uint32_t WtH[64][36];
    __shared__ uint32_t WtL[64][36];

    const int tid  = threadIdx.x;
    const int warp = tid >> 5;
    const int lane = tid & 31;
    const int g  = lane >> 2;
    const int qd = lane & 3;
    const int row_l = warp * 16 + g;

    float acc[8][4];
    #pragma unroll
    for (int j = 0; j < 8; j++) {
        acc[j][0]=0.f; acc[j][1]=0.f; acc[j][2]=0.f; acc[j][3]=0.f;
    }

    for (int k0 = 0; k0 < DD; k0 += 32) {
        for (int l = tid; l < 1024; l += 256) {
            int r = l >> 3, kq = l & 7;
            float4 v = *(const float4*)(x + (size_t)(m0 + r) * DD + k0 + kq * 4);
            uint32_t hx = f2tf(v.x), hy = f2tf(v.y), hz = f2tf(v.z), hw = f2tf(v.w);
            XsH[r][kq*4+0] = hx; XsH[r][kq*4+1] = hy;
            XsH[r][kq*4+2] = hz; XsH[r][kq*4+3] = hw;
            XsL[r][kq*4+0] = f2tf(v.x - __uint_as_float(hx));
            XsL[r][kq*4+1] = f2tf(v.y - __uint_as_float(hy));
            XsL[r][kq*4+2] = f2tf(v.z - __uint_as_float(hz));
            XsL[r][kq*4+3] = f2tf(v.w - __uint_as_float(hw));
        }
        for (int l = tid; l < 2048; l += 256) {
            int c = l & 63, k = l >> 6;
            float w = W[(size_t)(k0 + k) * DD + c0 + c];
            uint32_t h = f2tf(w);
            WtH[c][k] = h;
            WtL[c][k] = f2tf(w - __uint_as_float(h));
        }
        __syncthreads();

        #pragma unroll
        for (int kc = 0; kc < 32; kc += 8) {
            uint32_t aH0 = XsH[row_l    ][kc + qd];
            uint32_t aH1 = XsH[row_l + 8][kc + qd];
            uint32_t aH2 = XsH[row_l    ][kc + qd + 4];
            uint32_t aH3 = XsH[row_l + 8][kc + qd + 4];
            uint32_t aL0 = XsL[row_l    ][kc + qd];
            uint32_t aL1 = XsL[row_l + 8][kc + qd];
            uint32_t aL2 = XsL[row_l    ][kc + qd + 4];
            uint32_t aL3 = XsL[row_l + 8][kc + qd + 4];
            #pragma unroll
            for (int j = 0; j < 8; j++) {
                uint32_t bH0 = WtH[j*8 + g][kc + qd];
                uint32_t bH1 = WtH[j*8 + g][kc + qd + 4];
                uint32_t bL0 = WtL[j*8 + g][kc + qd];
                uint32_t bL1 = WtL[j*8 + g][kc + qd + 4];
                mma_tf32(acc[j][0], acc[j][1], acc[j][2], acc[j][3],
                         aH0, aH1, aH2, aH3, bH0, bH1);
                mma_tf32(acc[j][0], acc[j][1], acc[j][2], acc[j][3],
                         aH0, aH1, aH2, aH3, bL0, bL1);
                mma_tf32(acc[j][0], acc[j][1], acc[j][2], acc[j][3],
                         aL0, aL1, aL2, aL3, bH0, bH1);
            }
        }
        __syncthreads();
    }

    #pragma unroll
    for (int j = 0; j < 8; j++) {
        #pragma unroll
        for (int half = 0; half < 2; half++) {
            int m = m0 + row_l + half * 8;
            int b_ = m >> 11, n = m & 2047;
            int cbase = c0 + j*8 + qd*2;           // even -> both cols in same head
            int hh = cbase >> 5, d0 = cbase & 31;
            float v0 = acc[j][half*2 + 0] + bias[cbase];
            float v1 = acc[j][half*2 + 1] + bias[cbase + 1];
            size_t idx = ((size_t)(b_ * HH + hh) * NN + n) * HD + d0;
            if (mat == 0) {
                g_Q[idx] = v0; g_Q[idx + 1] = v1;
            } else if (mat == 1) {
                g_K[idx] = v0; g_K[idx + 1] = v1;
            } else {
                float cc = coeffs[hh * 4];
                g_acc[idx]     = cc * v0;
                g_acc[idx + 1] = cc * v1;
                // pack v rows (2e, 2e+1) -> bf16 pairs (lanes g even/odd exchange)
                float o0 = __shfl_xor_sync(0xffffffffu, v0, 4);
                float o1 = __shfl_xor_sync(0xffffffffu, v1, 4);
                if ((g & 1) == 0) {
                    size_t tix = ((size_t)(b_ * HH + hh) * (NN/2) + (n >> 1)) * HD + d0;
                    g_tb0[tix]     = pack_bf16(v0, o0);
                    g_tb0[tix + 1] = pack_bf16(v1, o1);
                }
            }
        }
    }
}

// ============================================================
// Kernel 2: P = exp(Q K^T * scale) -> bf16 (permuted layout) + rowsums.
// cp.async double-buffered K staging; K fed as raw fp32 (tf32-truncated).
// Epilogue stores coalesced uint4 (fragment-native sub-block permutation).
// grid (16 row-tiles of 128, 32 bh), block 256 (8 warps).
// ============================================================
__global__ void attnP_kernel() {
    const int bh = blockIdx.y;
    const int r0 = blockIdx.x * 128;

    __shared__ uint32_t Qs[128][36];      // tf32 (rna), scale folded
    __shared__ uint32_t Ks[2][128][36];   // raw fp32 bits via cp.async

    const int tid  = threadIdx.x;
    const int warp = tid >> 5;
    const int lane = tid & 31;
    const int g  = lane >> 2;   // 0..7
    const int qd = lane & 3;    // 0..3

    const float scale = 0.17677669529663687f;  // 1/sqrt(32), folded into Q

    const float* Qb = g_Q + ((size_t)bh * NN + r0) * HD;
    const float* Kb = g_K + (size_t)bh * NN * HD;

    for (int l = tid; l < 1024; l += 256) {
        int r = l >> 3, kq = l & 7;
        uint32_t s = (uint32_t)__cvta_generic_to_shared(&Ks[0][r][kq*4]);
        cp16(s, Kb + (size_t)r * HD + kq * 4);
    }
    asm volatile("cp.async.commit_group;");

    for (int l = tid; l < 1024; l += 256) {
        int r = l >> 3, kq = l & 7;
        float4 v = *(const float4*)(Qb + (size_t)r * HD + kq * 4);
        uint4 u;
        u.x = f2tf(v.x * scale); u.y = f2tf(v.y * scale);
        u.z = f2tf(v.z * scale); u.w = f2tf(v.w * scale);
        *(uint4*)&Qs[r][kq*4] = u;
    }

    const int row_l = warp * 16 + g;
    float rs_lo = 0.f, rs_hi = 0.f;

    for (int ct = 0; ct < 16; ct++) {
        const int c0 = ct * 128;
        const int buf = ct & 1;

        if (ct < 15) {
            const float* Kn = Kb + (size_t)(c0 + 128) * HD;
            for (int l = tid; l < 1024; l += 256) {
                int r = l >> 3, kq = l & 7;
                uint32_t s = (uint32_t)__cvta_generic_to_shared(&Ks[buf^1][r][kq*4]);
                cp16(s, Kn + (size_t)r * HD + kq * 4);
            }
            asm volatile("cp.async.commit_group;");
        }

        if (ct < 15) { asm volatile("cp.async.wait_group 1;"); }
        else         { asm volatile("cp.async.wait_group 0;"); }
        __syncthreads();

        float acc[16][4];
        #pragma unroll
        for (int j = 0; j < 16; j++) {
            acc[j][0] = 0.f; acc[j][1] = 0.f; acc[j][2] = 0.f; acc[j][3] = 0.f;
        }

        #pragma unroll
        for (int kc = 0; kc < 32; kc += 8) {
            uint32_t a0 = Qs[row_l    ][kc + qd];
            uint32_t a1 = Qs[row_l + 8][kc + qd];
            uint32_t a2 = Qs[row_l    ][kc + qd + 4];
            uint32_t a3 = Qs[row_l + 8][kc + qd + 4];
            #pragma unroll
            for (int j = 0; j < 16; j++) {
                uint32_t b0 = Ks[buf][j*8 + g][kc + qd];
                uint32_t b1 = Ks[buf][j*8 + g][kc + qd + 4];
                mma_tf32(acc[j][0], acc[j][1], acc[j][2], acc[j][3],
                         a0, a1, a2, a3, b0, b1);
            }
        }

        // epilogue: exp, pack, COALESCED permuted store, rowsum partials.
        // value for original pair-col (4*jl + qd) lands at offset qd*8 + jl.
        uint32_t* Pb = g_P + ((size_t)bh * NN + r0) * (NN/2) + ct*64;
        #pragma unroll
        for (int sb = 0; sb < 2; sb++) {
            uint32_t pls[8], phs[8];
            #pragma unroll
            for (int jl = 0; jl < 8; jl++) {
                int j = sb*8 + jl;
                float e0 = __expf(acc[j][0]);
                float e1 = __expf(acc[j][1]);
                float e2 = __expf(acc[j][2]);
                float e3 = __expf(acc[j][3]);
                pls[jl] = pack_bf16(e0, e1);
                phs[jl] = pack_bf16(e2, e3);
                rs_lo += e0 + e1;
                rs_hi += e2 + e3;
            }
            uint32_t* dst_lo = Pb + (size_t)(row_l    ) * (NN/2) + sb*32 + qd*8;
            uint32_t* dst_hi = Pb + (size_t)(row_l + 8) * (NN/2) + sb*32 + qd*8;
            __stcs((uint4*)dst_lo,       make_uint4(pls[0], pls[1], pls[2], pls[3]));
            __stcs((uint4*)(dst_lo + 4), make_uint4(pls[4], pls[5], pls[6], pls[7]));
            __stcs((uint4*)dst_hi,       make_uint4(phs[0], phs[1], phs[2], phs[3]));
            __stcs((uint4*)(dst_hi + 4), make_uint4(phs[4], phs[5], phs[6], phs[7]));
        }
        __syncthreads();
    }

    rs_lo += __shfl_xor_sync(0xffffffffu, rs_lo, 1);
    rs_lo += __shfl_xor_sync(0xffffffffu, rs_lo, 2);
    rs_hi += __shfl_xor_sync(0xffffffffu, rs_hi, 1);
    rs_hi += __shfl_xor_sync(0xffffffffu, rs_hi, 2);
    if (qd == 0) {
        g_rowsum[bh * NN + r0 + row_l]     = rs_lo;
        g_rowsum[bh * NN + r0 + row_l + 8] = rs_hi;
    }
}

// ============================================================
// Kernel 3: t_out = diag(1/rowsum) * P * t_in ; g_acc += c_k * t_out
// bf16 mma, cp.async double-buffered over 64-wide m-chunks.
// A-fragments read as 2x uint4 LDS from the permuted P layout:
//   stored offset qd*8 + jl  <->  pair-col 4*jl + qd
//   kc step kk uses stored offsets qd*8 + 2*kk (a0/a1) and +2*kk+1 (a2/a3).
// grid (16 row-tiles of 128, 32 bh), block 256 (8 warps).
// ============================================================
__global__ void pass_kernel(const float* __restrict__ coeffs, int pass) {
    __shared__ uint32_t Ps[2][128][36];   // permuted bf16 pairs; 64 m per chunk
    __shared__ uint32_t Ts[2][32][40];    // bf16 row-pairs of t chunk

    const uint32_t* tbin  = (pass & 1) ? g_tb0 : g_tb1;
    uint32_t*       tbout = (pass & 1) ? g_tb1 : g_tb0;

    const int bh = blockIdx.y;
    const int r0 = blockIdx.x * 128;
    const float c = coeffs[(bh & 7) * 4 + pass];

    const int tid  = threadIdx.x;
    const int warp = tid >> 5;
    const int lane = tid & 31;
    const int g  = lane >> 2;
    const int qd = lane & 3;

    float acc[4][4];
    #pragma unroll
    for (int j = 0; j < 4; j++) {
        acc[j][0]=0.f; acc[j][1]=0.f; acc[j][2]=0.f; acc[j][3]=0.f;
    }

    const uint32_t* Prow = g_P + ((size_t)bh * NN + r0) * (NN/2);
    const uint32_t* Tbb  = tbin + (size_t)bh * (NN/2) * HD;
    const int row_l = warp * 16 + g;

    // prologue: async-load P chunk 0 + t chunk 0 as one group
    for (int l = tid; l < 1024; l += 256) {
        int r = l >> 3, mq = l & 7;
        uint32_t s = (uint32_t)__cvta_generic_to_shared(&Ps[0][r][mq*4]);
        cp16(s, Prow + (size_t)r * (NN/2) + mq*4);
    }
    {
        int m2 = tid >> 3, mq = tid & 7;
        uint32_t s = (uint32_t)__cvta_generic_to_shared(&Ts[0][m2][mq*4]);
        cp16(s, Tbb + (size_t)m2 * HD + mq*4);
    }
    asm volatile("cp.async.commit_group;");

    for (int i = 0; i < 32; i++) {
        const int buf = i & 1;

        // issue async load of next P + t chunk into the other buffer
        if (i < 31) {
            const uint32_t* Pg = Prow + (i + 1) * 32;
            for (int l = tid; l < 1024; l += 256) {
                int r = l >> 3, mq = l & 7;
                uint32_t s = (uint32_t)__cvta_generic_to_shared(&Ps[buf^1][r][mq*4]);
                cp16(s, Pg + (size_t)r * (NN/2) + mq*4);
            }
            const uint32_t* Tg = Tbb + (size_t)(i + 1) * 32 * HD;
            {
                int m2 = tid >> 3, mq = tid & 7;
                uint32_t s = (uint32_t)__cvta_generic_to_shared(&Ts[buf^1][m2][mq*4]);
                cp16(s, Tg + (size_t)m2 * HD + mq*4);
            }
            asm volatile("cp.async.commit_group;");
        }

        if (i < 31) { asm volatile("cp.async.wait_group 1;"); }
        else        { asm volatile("cp.async.wait_group 0;"); }
        __syncthreads();

        // A-fragments: 2x uint4 per row from permuted layout
        const uint32_t* sl = &Ps[buf][row_l    ][qd*8];
        const uint32_t* sh = &Ps[buf][row_l + 8][qd*8];
        uint4 L0 = *(const uint4*)sl;
        uint4 L1 = *(const uint4*)(sl + 4);
        uint4 H0 = *(const uint4*)sh;
        uint4 H1 = *(const uint4*)(sh + 4);
        uint32_t A[4][4] = {
            {L0.x, H0.x, L0.y, H0.y},   // kc = 0
            {L0.z, H0.z, L0.w, H0.w},   // kc = 8
            {L1.x, H1.x, L1.y, H1.y},   // kc = 16
            {L1.z, H1.z, L1.w, H1.w},   // kc = 24
        };

        #pragma unroll
        for (int kk = 0; kk < 4; kk++) {
            const int kc = kk * 8;
            #pragma unroll
            for (int j = 0; j < 4; j++) {
                uint32_t b0 = Ts[buf][kc + qd    ][j*8 + g];
                uint32_t b1 = Ts[buf][kc + qd + 4][j*8 + g];
                mma_bf16(acc[j][0], acc[j][1], acc[j][2], acc[j][3],
                         A[kk][0], A[kk][1], A[kk][2], A[kk][3], b0, b1);
            }
        }
        __syncthreads();
    }

    const int r_lo = r0 + row_l;
    const int r_hi = r_lo + 8;
    const float inv_lo = 1.0f / g_rowsum[bh * NN + r_lo];
    const float inv_hi = 1.0f / g_rowsum[bh * NN + r_hi];
    #pragma unroll
    for (int j = 0; j < 4; j++) {
        int col = j*8 + qd*2;
        size_t o_lo = ((size_t)bh * NN + r_lo) * HD + col;
        size_t o_hi = ((size_t)bh * NN + r_hi) * HD + col;
        float2 lo = make_float2(acc[j][0] * inv_lo, acc[j][1] * inv_lo);
        float2 hi = make_float2(acc[j][2] * inv_hi, acc[j][3] * inv_hi);
        // g_acc RMW (fp32, exact)
        float2 a_lo = *(float2*)(g_acc + o_lo);
        float2 a_hi = *(float2*)(g_acc + o_hi);
        a_lo.x += c * lo.x; a_lo.y += c * lo.y;
        a_hi.x += c * hi.x; a_hi.y += c * hi.y;
        *(float2*)(g_acc + o_lo) = a_lo;
        *(float2*)(g_acc + o_hi) = a_hi;
        // t_out as bf16 row-pairs (skip on final pass)
        if (pass != 3) {
            float olx = __shfl_xor_sync(0xffffffffu, lo.x, 4);
            float oly = __shfl_xor_sync(0xffffffffu, lo.y, 4);
            float ohx = __shfl_xor_sync(0xffffffffu, hi.x, 4);
            float ohy = __shfl_xor_sync(0xffffffffu, hi.y, 4);
            if ((g & 1) == 0) {
                size_t t_lo = ((size_t)bh * (NN/2) + (r_lo >> 1)) * HD + col;
                size_t t_hi = ((size_t)bh * (NN/2) + (r_hi >> 1)) * HD + col;
                tbout[t_lo]     = pack_bf16(lo.x, olx);
                tbout[t_lo + 1] = pack_bf16(lo.y, oly);
                tbout[t_hi]     = pack_bf16(hi.x, ohx);
                tbout[t_hi + 1] = pack_bf16(hi.y, ohy);
            }
        }
    }
}

// ============================================================
// Kernel 4: out = merged(g_acc) @ Wo + bo  (scalar fp32 — small)
// grid (128, 4), block 256.
// ============================================================
__global__ void outproj_kernel(const float* __restrict__ Wo,
                               const float* __restrict__ bo,
                               float* __restrict__ out) {
    const int m0 = blockIdx.x * 64;
    const int c0 = blockIdx.y * 64;

    __shared__ float Ms[64][33];
    __shared__ float Ws[32][64];

    const int tid = threadIdx.x;
    const int ty = tid >> 4, tx = tid & 15;

    float acc[4][4] = {};

    for (int k0 = 0; k0 < DD; k0 += 32) {
        int hh = k0 >> 5;
        for (int l = tid; l < 512; l += 256) {
            int r = l >> 3, kq = l & 7;
            int m = m0 + r;
            int b_ = m >> 11, n = m & 2047;
            float4 v = *(const float4*)(g_acc + ((size_t)(b_ * HH + hh) * NN + n) * HD + kq * 4);
            Ms[r][kq*4+0] = v.x; Ms[r][kq*4+1] = v.y;
            Ms[r][kq*4+2] = v.z; Ms[r][kq*4+3] = v.w;
        }
        for (int l = tid; l < 512; l += 256) {
            int k = l >> 4, cq = l & 15;
            *(float4*)&Ws[k][cq*4] = *(const float4*)(Wo + (size_t)(k0 + k) * DD + c0 + cq * 4);
        }
        __syncthreads();
        #pragma unroll
        for (int kk = 0; kk < 32; kk++) {
            float a0 = Ms[ty*4+0][kk];
            float a1 = Ms[ty*4+1][kk];
            float a2 = Ms[ty*4+2][kk];
            float a3 = Ms[ty*4+3][kk];
            float4 b = *(float4*)&Ws[kk][tx*4];
            acc[0][0] += a0*b.x; acc[0][1] += a0*b.y; acc[0][2] += a0*b.z; acc[0][3] += a0*b.w;
            acc[1][0] += a1*b.x; acc[1][1] += a1*b.y; acc[1][2] += a1*b.z; acc[1][3] += a1*b.w;
            acc[2][0] += a2*b.x; acc[2][1] += a2*b.y; acc[2][2] += a2*b.z; acc[2][3] += a2*b.w;
            acc[3][0] += a3*b.x; acc[3][1] += a3*b.y; acc[3][2] += a3*b.z; acc[3][3] += a3*b.w;
        }
        __syncthreads();
    }

    #pragma unroll
    for (int i = 0; i < 4; i++) {
        int m = m0 + ty * 4 + i;
        #pragma unroll
        for (int j = 0; j < 4; j++) {
            int cc = c0 + tx * 4 + j;
            out[(size_t)m * DD + cc] = acc[i][j] + bo[cc];
        }
    }
}

// ============================================================
extern "C" void kernel_launch(void* const* d_in, const int* in_sizes, int n_in,
                              void* d_out, int out_size) {
    const float* x      = (const float*)d_in[0];
    const float* Wq     = (const float*)d_in[1];
    const float* bq     = (const float*)d_in[2];
    const float* Wk     = (const float*)d_in[3];
    const float* bk     = (const float*)d_in[4];
    const float* Wv     = (const float*)d_in[5];
    const float* bv     = (const float*)d_in[6];
    const float* Wo     = (const float*)d_in[7];
    const float* bo     = (const float*)d_in[8];
    const float* coeffs = (const float*)d_in[9];
    float* out = (float*)d_out;

    dim3 g1(64, 4, 3);
    qkv_kernel<<<g1, 256>>>(x, Wq, bq, Wk, bk, Wv, bv, coeffs);

    dim3 g2(16, 32);
    attnP_kernel<<<g2, 256>>>();

    pass_kernel<<<g2, 256>>>(coeffs, 1);
    pass_kernel<<<g2, 256>>>(coeffs, 2);
    pass_kernel<<<g2, 256>>>(coeffs, 3);

    dim3 g4(128, 4);
    outproj_kernel<<<g4, 256>>>(Wo, bo, out);
}